// round 14
// baseline (speedup 1.0000x reference)
#include <cuda_runtime.h>
#include <cuda_fp16.h>
#include <stdint.h>

// ---------------- problem constants ----------------
#define B_TOT   4096
#define F0N     39
#define DN      16
#define NT      256

#define K0TOT   1521      // 39*39
#define K0PAD   1536      // 48 chunks of 32
#define K1TOT   2496      // 39*64
#define K1PAD   2496      // 78 chunks of 32

#define BK      32        // K per chunk (fp16 elems)
#define ROWB    80        // tile row stride bytes (64B data + 16B pad; 16B-aligned)
#define IPADH   42        // xt row stride in halves (39 data) -> 84B, word stride 21 (odd)
#define JPADH   66        // ht row stride in halves (64 data) -> 132B, word stride 33 (odd)

// ---------------- global scratch ----------------
__device__ __half g_h[B_TOT * 64 * DN];     // fp16 h between layers
__device__ __half g_w0hi[128 * K0PAD];
__device__ __half g_w0lo[128 * K0PAD];
__device__ __half g_w1hi[128 * K1PAD];
__device__ __half g_w1lo[128 * K1PAD];

// ---------------- PTX helpers ----------------
__device__ __forceinline__ uint32_t smem_to_u32(const void* p) {
    uint32_t a;
    asm("{ .reg .u64 t; cvta.to.shared.u64 t, %1; cvt.u32.u64 %0, t; }" : "=r"(a) : "l"(p));
    return a;
}

__device__ __forceinline__ void ldsm4(uint32_t* r, uint32_t addr) {
    asm volatile("ldmatrix.sync.aligned.m8n8.x4.shared.b16 {%0,%1,%2,%3}, [%4];"
        : "=r"(r[0]), "=r"(r[1]), "=r"(r[2]), "=r"(r[3]) : "r"(addr));
}

__device__ __forceinline__ void mma_f16(float* c, const uint32_t* a, uint32_t b0, uint32_t b1) {
    asm volatile(
        "mma.sync.aligned.m16n8k16.row.col.f32.f16.f16.f32 "
        "{%0,%1,%2,%3}, {%4,%5,%6,%7}, {%8,%9}, {%0,%1,%2,%3};"
        : "+f"(c[0]), "+f"(c[1]), "+f"(c[2]), "+f"(c[3])
        : "r"(a[0]), "r"(a[1]), "r"(a[2]), "r"(a[3]), "r"(b0), "r"(b1));
}

#define CP_ASYNC16(saddr, gptr) \
    asm volatile("cp.async.cg.shared.global [%0], [%1], 16;" \
        :: "r"((uint32_t)(saddr)), "l"(gptr))
#define CP_COMMIT()  asm volatile("cp.async.commit_group;" ::: "memory")
#define CP_WAIT0()   asm volatile("cp.async.wait_group 0;"  ::: "memory")

__device__ __forceinline__ uint32_t pack_half2(float p0, float p1) {
    __half2 q = __float22half2_rn(make_float2(p0, p1));
    return *reinterpret_cast<uint32_t*>(&q);
}

// ---------------- W pre-split: f[k][128] -> g_w{hi,lo} fp16 [n=128][KPAD], zero-padded ----------------
template<int LAYER>
__global__ void __launch_bounds__(256)
convert_w_kernel(const float* __restrict__ f)
{
    constexpr int KTOT = (LAYER == 0) ? K0TOT : K1TOT;
    constexpr int KPAD = (LAYER == 0) ? K0PAD : K1PAD;
    __half* whi = (LAYER == 0) ? g_w0hi : g_w1hi;
    __half* wlo = (LAYER == 0) ? g_w0lo : g_w1lo;

    int idx = blockIdx.x * blockDim.x + threadIdx.x;
    if (idx >= 128 * KPAD) return;
    int n = idx / KPAD;
    int k = idx - n * KPAD;
    float v = (k < KTOT) ? f[k * 128 + n] : 0.0f;
    __half h = __float2half_rn(v);
    whi[idx] = h;
    wlo[idx] = __float2half_rn(v - __half2float(h));
}

// ---------------- main fused layer kernel (fp16 HMMA, 2-term, A+B double-buffered) ----------------
// LAYER 0: h == x (FK=39), writes relu(z[:, :64]) to g_h (fp16), out = bias + sum z[:,64:]*dw[0:64]
// LAYER 1: h from g_h (FK=64), out += sum z * dw[64:192]
template<int FK, int KTOT, int KPAD, int LAYER>
__global__ void __launch_bounds__(NT, 2)
cin_mma_kernel(const float* __restrict__ x,
               const float* __restrict__ dw,
               const float* __restrict__ db,
               float* __restrict__ out)
{
    extern __shared__ char smem[];

    constexpr int OFF_DW   = 0;                    // 192 floats
    constexpr int OFF_SOUT = 768;                  // 8 floats
    constexpr int OFF_XT   = 1024;                 // fp16 [128][IPADH]
    constexpr int XT_BYTES = 128 * IPADH * 2;      // 10752
    constexpr int OFF_HT   = OFF_XT + XT_BYTES;    // 11776
    constexpr int HT_BYTES = (LAYER == 1) ? 128 * JPADH * 2 : 0;
    constexpr int OFF_T    = ((OFF_HT + HT_BYTES + 1023) / 1024) * 1024;
    constexpr int TILE     = 128 * ROWB;           // 10240
    constexpr int OFF_A    = OFF_T;                // A: 2 bufs
    constexpr int OFF_B    = OFF_T + 2 * TILE;     // B: 2 bufs x (hi, lo)
    constexpr int BBUF     = 2 * TILE;
    constexpr int NCHUNKS  = KPAD / BK;

    const __half* __restrict__ whi = (LAYER == 0) ? g_w0hi : g_w1hi;
    const __half* __restrict__ wlo = (LAYER == 0) ? g_w0lo : g_w1lo;

    const uint32_t smem_u = smem_to_u32(smem);
    float*  s_dw  = (float*)(smem + OFF_DW);
    float*  s_out = (float*)(smem + OFF_SOUT);
    __half* xt    = (__half*)(smem + OFF_XT);
    __half* ht    = (LAYER == 0) ? xt : (__half*)(smem + OFF_HT);
    constexpr int HSTR = (LAYER == 0) ? IPADH : JPADH;

    const int tid  = threadIdx.x;
    const int wid  = tid >> 5;
    const int lane = tid & 31;
    const int b0   = blockIdx.x * 8;

    const int srow = tid >> 2;     // 0..63 (+part*64)
    const int skt  = tid & 3;      // 0..3 (8 fp16 = 16B each)

    // issue B chunk (hi+lo) into buffer pbuf via cp.async
    auto issue_b = [&](int k0n, int pbuf) {
        uint32_t bhi = smem_u + OFF_B + pbuf * BBUF;
        uint32_t blo = bhi + TILE;
#pragma unroll
        for (int p = 0; p < 2; p++) {
            int n = srow + p * 64;
            uint32_t so = (uint32_t)(n * ROWB + skt * 16);
            CP_ASYNC16(bhi + so, whi + (size_t)n * KPAD + k0n + skt * 8);
            CP_ASYNC16(blo + so, wlo + (size_t)n * KPAD + k0n + skt * 8);
        }
    };

    // ---- prefetch B(0) before anything else ----
    issue_b(0, 0);
    CP_COMMIT();

    // ---- stage x transposed (fp16): xt[row][i], row = bl*16 + d ----
    for (int e = tid; e < 8 * F0N * DN; e += NT) {
        int bl = e / (F0N * DN);
        int rem = e - bl * (F0N * DN);
        int i = rem >> 4, d = rem & 15;
        xt[(bl * 16 + d) * IPADH + i] = __float2half_rn(x[(size_t)(b0) * (F0N * DN) + e]);
    }
    if (LAYER == 1) {
        for (int e = tid; e < 8 * 64 * 16; e += NT) {
            int bl = e >> 10;
            int j  = (e >> 4) & 63;
            int d  = e & 15;
            ht[(bl * 16 + d) * JPADH + j] = g_h[(size_t)b0 * 1024 + e];
        }
    }
    if (tid < 192) s_dw[tid] = dw[tid];
    if (tid < 8)   s_out[tid] = 0.0f;
    __syncthreads();

    // build A chunk (single fp16) for k-base k0n into buffer pbuf
    auto build_a = [&](int k0n, int pbuf) {
        char* Abuf = smem + OFF_A + pbuf * TILE;
#pragma unroll
        for (int p = 0; p < 2; p++) {
            int row = srow + p * 64;
            int kb  = k0n + skt * 8;
            const __half* xr = xt + row * IPADH;
            const __half* hr = ht + row * HSTR;
            uint32_t hp[4];
#pragma unroll
            for (int v = 0; v < 4; v++) {
                float p0 = 0.0f, p1 = 0.0f;
                int ka = kb + 2 * v;
                if (KPAD == KTOT || ka < KTOT) {
                    int i = ka / FK, j = ka - i * FK;
                    p0 = __half2float(xr[i]) * __half2float(hr[j]);
                }
                if (KPAD == KTOT || (ka + 1) < KTOT) {
                    int i = (ka + 1) / FK, j = (ka + 1) - i * FK;
                    p1 = __half2float(xr[i]) * __half2float(hr[j]);
                }
                hp[v] = pack_half2(p0, p1);
            }
            *(uint4*)(Abuf + row * ROWB + skt * 16) = make_uint4(hp[0], hp[1], hp[2], hp[3]);
        }
    };

    // warp tiling: 4 (M) x 2 (N); warp tile 32 x 64
    const int wm = wid >> 1;
    const int wn = wid & 1;
    const int m0 = wm * 32;
    const int n0 = wn * 64;

    float acc[2][8][4];
#pragma unroll
    for (int mt = 0; mt < 2; mt++)
#pragma unroll
        for (int nt = 0; nt < 8; nt++)
#pragma unroll
            for (int r = 0; r < 4; r++) acc[mt][nt][r] = 0.0f;

    const int lrow = (lane & 7) + ((lane >> 3) & 1) * 8;
    const int lkb  = (lane >> 4) * 16;

    // ---- prologue: A(0); B(0) already in flight ----
    build_a(0, 0);
    CP_WAIT0();
    __syncthreads();

    for (int ch = 0; ch < NCHUNKS; ch++) {
        const int p = ch & 1;
        const bool have_next = (ch + 1 < NCHUNKS);

        // prefetch B(ch+1) into the other buffer; lands during MMA+build below
        if (have_next) { issue_b((ch + 1) * BK, p ^ 1); CP_COMMIT(); }

        // ---- MMA phase on A(p) + B(p): 2 k16-steps ----
        const uint32_t a_u   = smem_u + OFF_A + p * TILE;
        const uint32_t bhi_u = smem_u + OFF_B + p * BBUF;
        const uint32_t blo_u = bhi_u + TILE;
#pragma unroll
        for (int ks = 0; ks < 2; ks++) {
            const uint32_t kcb = (uint32_t)(ks * 32 + lkb);
            uint32_t av[2][4];
#pragma unroll
            for (int mt = 0; mt < 2; mt++)
                ldsm4(av[mt], a_u + (uint32_t)((m0 + mt * 16 + lrow) * ROWB) + kcb);
#pragma unroll
            for (int nt2 = 0; nt2 < 4; nt2++) {
                uint32_t rb = (uint32_t)((n0 + nt2 * 16 + lrow) * ROWB) + kcb;
                uint32_t bh[4], bl[4];
                ldsm4(bh, bhi_u + rb);
                ldsm4(bl, blo_u + rb);
#pragma unroll
                for (int mt = 0; mt < 2; mt++) {
#pragma unroll
                    for (int sub = 0; sub < 2; sub++) {
                        float* c = acc[mt][nt2 * 2 + sub];
                        mma_f16(c, av[mt], bh[sub], bh[sub + 2]);   // A * Bhi
                        mma_f16(c, av[mt], bl[sub], bl[sub + 2]);   // A * Blo
                    }
                }
            }
        }

        // ---- build A(ch+1) into the other buffer (off the MMA critical path) ----
        if (have_next) {
            build_a((ch + 1) * BK, p ^ 1);
            CP_WAIT0();                  // B(ch+1) landed
        }
        __syncthreads();                 // one barrier per chunk
    }

    // ---- epilogue: relu, h-store (layer 0, fp16), weighted reduce ----
    const int qrow = lane >> 2;
    const int qcol = (lane & 3) * 2;
#pragma unroll
    for (int mt = 0; mt < 2; mt++) {
        const int bl = wm * 2 + mt;
        const int b  = b0 + bl;
        float partial = 0.0f;
#pragma unroll
        for (int nt = 0; nt < 8; nt++) {
#pragma unroll
            for (int r = 0; r < 4; r++) {
                int d = qrow + 8 * (r >> 1);
                int n = n0 + nt * 8 + qcol + (r & 1);
                float v = fmaxf(acc[mt][nt][r], 0.0f);
                if (LAYER == 0) {
                    if (n < 64)
                        g_h[((size_t)b * 64 + n) * 16 + d] = __float2half_rn(v);
                    else
                        partial = fmaf(v, s_dw[n - 64], partial);
                } else {
                    partial = fmaf(v, s_dw[64 + n], partial);
                }
            }
        }
        atomicAdd(&s_out[bl], partial);
    }
    __syncthreads();
    if (tid < 8) {
        if (LAYER == 0) out[b0 + tid] = s_out[tid] + db[0];
        else            out[b0 + tid] += s_out[tid];
    }
}

// ---------------- launch ----------------
extern "C" void kernel_launch(void* const* d_in, const int* in_sizes, int n_in,
                              void* d_out, int out_size)
{
    const float* x  = (const float*)d_in[0];   // [4096][39][16]
    const float* f0 = (const float*)d_in[1];   // [1521][128]
    const float* f1 = (const float*)d_in[2];   // [2496][128]
    const float* dw = (const float*)d_in[3];   // [192]
    const float* db = (const float*)d_in[4];   // [1]
    float* out = (float*)d_out;                // [4096]

    convert_w_kernel<0><<<(128 * K0PAD + 255) / 256, 256>>>(f0);
    convert_w_kernel<1><<<(128 * K1PAD + 255) / 256, 256>>>(f1);

    constexpr int TILE = 128 * ROWB;
    constexpr int XT_BYTES = 128 * IPADH * 2;
    constexpr int HT_BYTES = 128 * JPADH * 2;
    constexpr int OFF_T0 = ((1024 + XT_BYTES + 1023) / 1024) * 1024;              // 12288
    constexpr int OFF_T1 = ((1024 + XT_BYTES + HT_BYTES + 1023) / 1024) * 1024;   // 28672
    const int smem0 = OFF_T0 + 6 * TILE;   // 73728  (72 KB)  -> 2 CTAs/SM
    const int smem1 = OFF_T1 + 6 * TILE;   // 90112  (88 KB)  -> 2 CTAs/SM

    cudaFuncSetAttribute(cin_mma_kernel<39, K0TOT, K0PAD, 0>,
                         cudaFuncAttributeMaxDynamicSharedMemorySize, smem0);
    cudaFuncSetAttribute(cin_mma_kernel<64, K1TOT, K1PAD, 1>,
                         cudaFuncAttributeMaxDynamicSharedMemorySize, smem1);

    dim3 grid(B_TOT / 8);
    dim3 block(NT);
    cin_mma_kernel<39, K0TOT, K0PAD, 0><<<grid, block, smem0>>>(x, dw, db, out);
    cin_mma_kernel<64, K1TOT, K1PAD, 1><<<grid, block, smem1>>>(x, dw, db, out);
}

// round 15
// speedup vs baseline: 1.4891x; 1.4891x over previous
#include <cuda_runtime.h>
#include <cuda_fp16.h>
#include <stdint.h>

// ---------------- problem constants ----------------
#define B_TOT   4096
#define F0N     39
#define DN      16
#define NT      256

#define K0TOT   1521      // 39*39
#define K0PAD   1536      // 48 chunks of 32
#define K1TOT   2496      // 39*64
#define K1PAD   2496      // 78 chunks of 32

#define BK      32        // K per chunk (fp16 elems)
#define ROWB    80        // tile row stride bytes (64B data + 16B pad; 16B-aligned)
#define IPADH   42        // xt row stride in halves (39 data)
#define JPADH   66        // ht row stride in halves (64 data)

// ---------------- global scratch ----------------
__device__ __half g_h[B_TOT * 64 * DN];     // fp16 h between layers
__device__ __half g_w0[128 * K0PAD];        // fp16 W, [n][KPAD], zero-padded
__device__ __half g_w1[128 * K1PAD];

// ---------------- PTX helpers ----------------
__device__ __forceinline__ uint32_t smem_to_u32(const void* p) {
    uint32_t a;
    asm("{ .reg .u64 t; cvta.to.shared.u64 t, %1; cvt.u32.u64 %0, t; }" : "=r"(a) : "l"(p));
    return a;
}

__device__ __forceinline__ void ldsm4(uint32_t* r, uint32_t addr) {
    asm volatile("ldmatrix.sync.aligned.m8n8.x4.shared.b16 {%0,%1,%2,%3}, [%4];"
        : "=r"(r[0]), "=r"(r[1]), "=r"(r[2]), "=r"(r[3]) : "r"(addr));
}

__device__ __forceinline__ void mma_f16(float* c, const uint32_t* a, uint32_t b0, uint32_t b1) {
    asm volatile(
        "mma.sync.aligned.m16n8k16.row.col.f32.f16.f16.f32 "
        "{%0,%1,%2,%3}, {%4,%5,%6,%7}, {%8,%9}, {%0,%1,%2,%3};"
        : "+f"(c[0]), "+f"(c[1]), "+f"(c[2]), "+f"(c[3])
        : "r"(a[0]), "r"(a[1]), "r"(a[2]), "r"(a[3]), "r"(b0), "r"(b1));
}

#define CP_ASYNC16(saddr, gptr) \
    asm volatile("cp.async.cg.shared.global [%0], [%1], 16;" \
        :: "r"((uint32_t)(saddr)), "l"(gptr))
#define CP_COMMIT()  asm volatile("cp.async.commit_group;" ::: "memory")
#define CP_WAIT0()   asm volatile("cp.async.wait_group 0;"  ::: "memory")

__device__ __forceinline__ uint32_t pack_half2(float p0, float p1) {
    __half2 q = __float22half2_rn(make_float2(p0, p1));
    return *reinterpret_cast<uint32_t*>(&q);
}

// ---------------- W convert: f[k][128] -> fp16 [n=128][KPAD], zero-padded ----------------
template<int LAYER>
__global__ void __launch_bounds__(256)
convert_w_kernel(const float* __restrict__ f)
{
    constexpr int KTOT = (LAYER == 0) ? K0TOT : K1TOT;
    constexpr int KPAD = (LAYER == 0) ? K0PAD : K1PAD;
    __half* w = (LAYER == 0) ? g_w0 : g_w1;

    int idx = blockIdx.x * blockDim.x + threadIdx.x;
    if (idx >= 128 * KPAD) return;
    int n = idx / KPAD;
    int k = idx - n * KPAD;
    float v = (k < KTOT) ? f[k * 128 + n] : 0.0f;
    w[idx] = __float2half_rn(v);
}

// ---------------- main fused layer kernel (fp16 HMMA, single-term) ----------------
// LAYER 0: h == x (FK=39), writes relu(z[:, :64]) to g_h (fp16), out = bias + sum z[:,64:]*dw[0:64]
// LAYER 1: h from g_h (FK=64), out += sum z * dw[64:192]
template<int FK, int KTOT, int KPAD, int LAYER>
__global__ void __launch_bounds__(NT, 2)
cin_mma_kernel(const float* __restrict__ x,
               const float* __restrict__ dw,
               const float* __restrict__ db,
               float* __restrict__ out)
{
    extern __shared__ char smem[];

    constexpr int OFF_DW   = 0;                    // 192 floats
    constexpr int OFF_SOUT = 768;                  // 8 floats
    constexpr int OFF_XT   = 1024;                 // fp16 [128][IPADH]
    constexpr int XT_BYTES = 128 * IPADH * 2;      // 10752
    constexpr int OFF_HT   = OFF_XT + XT_BYTES;    // 11776
    constexpr int HT_BYTES = (LAYER == 1) ? 128 * JPADH * 2 : 0;
    constexpr int OFF_T    = ((OFF_HT + HT_BYTES + 1023) / 1024) * 1024;
    constexpr int TILE     = 128 * ROWB;           // 10240
    constexpr int OFF_A    = OFF_T;                // A: 2 bufs
    constexpr int OFF_B    = OFF_T + 2 * TILE;     // B: 2 bufs
    constexpr int NCHUNKS  = KPAD / BK;

    const __half* __restrict__ wsrc = (LAYER == 0) ? g_w0 : g_w1;

    const uint32_t smem_u = smem_to_u32(smem);
    float*  s_dw  = (float*)(smem + OFF_DW);
    float*  s_out = (float*)(smem + OFF_SOUT);
    __half* xt    = (__half*)(smem + OFF_XT);
    __half* ht    = (LAYER == 0) ? xt : (__half*)(smem + OFF_HT);
    constexpr int HSTR = (LAYER == 0) ? IPADH : JPADH;

    const int tid  = threadIdx.x;
    const int wid  = tid >> 5;
    const int lane = tid & 31;
    const int b0   = blockIdx.x * 8;

    const int srow = tid >> 2;     // 0..63 (+part*64)
    const int skt  = tid & 3;      // 0..3 (8 fp16 = 16B each)

    // issue B chunk into buffer pbuf via cp.async
    auto issue_b = [&](int k0n, int pbuf) {
        uint32_t bb = smem_u + OFF_B + pbuf * TILE;
#pragma unroll
        for (int p = 0; p < 2; p++) {
            int n = srow + p * 64;
            uint32_t so = (uint32_t)(n * ROWB + skt * 16);
            CP_ASYNC16(bb + so, wsrc + (size_t)n * KPAD + k0n + skt * 8);
        }
    };

    // ---- prefetch B(0) before anything else ----
    issue_b(0, 0);
    CP_COMMIT();

    // ---- stage x transposed (fp16): xt[row][i], row = bl*16 + d ----
    for (int e = tid; e < 8 * F0N * DN; e += NT) {
        int bl = e / (F0N * DN);
        int rem = e - bl * (F0N * DN);
        int i = rem >> 4, d = rem & 15;
        xt[(bl * 16 + d) * IPADH + i] = __float2half_rn(x[(size_t)(b0) * (F0N * DN) + e]);
    }
    if (LAYER == 1) {
        for (int e = tid; e < 8 * 64 * 16; e += NT) {
            int bl = e >> 10;
            int j  = (e >> 4) & 63;
            int d  = e & 15;
            ht[(bl * 16 + d) * JPADH + j] = g_h[(size_t)b0 * 1024 + e];
        }
    }
    if (tid < 192) s_dw[tid] = dw[tid];
    if (tid < 8)   s_out[tid] = 0.0f;
    __syncthreads();

    // build A chunk (fp16) for k-base k0n into buffer pbuf
    auto build_a = [&](int k0n, int pbuf) {
        char* Abuf = smem + OFF_A + pbuf * TILE;
#pragma unroll
        for (int p = 0; p < 2; p++) {
            int row = srow + p * 64;
            int kb  = k0n + skt * 8;
            const __half* xr = xt + row * IPADH;
            const __half* hr = ht + row * HSTR;
            uint32_t hp[4];
#pragma unroll
            for (int v = 0; v < 4; v++) {
                float p0 = 0.0f, p1 = 0.0f;
                int ka = kb + 2 * v;
                if (KPAD == KTOT || ka < KTOT) {
                    int i = ka / FK, j = ka - i * FK;
                    p0 = __half2float(xr[i]) * __half2float(hr[j]);
                }
                if (KPAD == KTOT || (ka + 1) < KTOT) {
                    int i = (ka + 1) / FK, j = (ka + 1) - i * FK;
                    p1 = __half2float(xr[i]) * __half2float(hr[j]);
                }
                hp[v] = pack_half2(p0, p1);
            }
            *(uint4*)(Abuf + row * ROWB + skt * 16) = make_uint4(hp[0], hp[1], hp[2], hp[3]);
        }
    };

    // warp tiling: 4 (M) x 2 (N); warp tile 32 x 64
    const int wm = wid >> 1;
    const int wn = wid & 1;
    const int m0 = wm * 32;
    const int n0 = wn * 64;

    float acc[2][8][4];
#pragma unroll
    for (int mt = 0; mt < 2; mt++)
#pragma unroll
        for (int nt = 0; nt < 8; nt++)
#pragma unroll
            for (int r = 0; r < 4; r++) acc[mt][nt][r] = 0.0f;

    const int lrow = (lane & 7) + ((lane >> 3) & 1) * 8;
    const int lkb  = (lane >> 4) * 16;

    // ---- prologue: A(0); B(0) already in flight ----
    build_a(0, 0);
    CP_WAIT0();
    __syncthreads();

    for (int ch = 0; ch < NCHUNKS; ch++) {
        const int p = ch & 1;
        const bool have_next = (ch + 1 < NCHUNKS);

        // prefetch B(ch+1); lands during MMA+build below
        if (have_next) { issue_b((ch + 1) * BK, p ^ 1); CP_COMMIT(); }

        // ---- MMA phase on A(p) + B(p): 2 k16-steps ----
        const uint32_t a_u = smem_u + OFF_A + p * TILE;
        const uint32_t b_u = smem_u + OFF_B + p * TILE;
#pragma unroll
        for (int ks = 0; ks < 2; ks++) {
            const uint32_t kcb = (uint32_t)(ks * 32 + lkb);
            uint32_t av[2][4];
#pragma unroll
            for (int mt = 0; mt < 2; mt++)
                ldsm4(av[mt], a_u + (uint32_t)((m0 + mt * 16 + lrow) * ROWB) + kcb);
#pragma unroll
            for (int nt2 = 0; nt2 < 4; nt2++) {
                uint32_t rb = (uint32_t)((n0 + nt2 * 16 + lrow) * ROWB) + kcb;
                uint32_t bh[4];
                ldsm4(bh, b_u + rb);
#pragma unroll
                for (int mt = 0; mt < 2; mt++) {
#pragma unroll
                    for (int sub = 0; sub < 2; sub++) {
                        mma_f16(acc[mt][nt2 * 2 + sub], av[mt], bh[sub], bh[sub + 2]);
                    }
                }
            }
        }

        // ---- build A(ch+1) into the other buffer ----
        if (have_next) {
            build_a((ch + 1) * BK, p ^ 1);
            CP_WAIT0();                  // B(ch+1) landed
        }
        __syncthreads();                 // one barrier per chunk
    }

    // ---- epilogue: relu, h-store (layer 0, fp16), weighted reduce ----
    const int qrow = lane >> 2;
    const int qcol = (lane & 3) * 2;
#pragma unroll
    for (int mt = 0; mt < 2; mt++) {
        const int bl = wm * 2 + mt;
        const int b  = b0 + bl;
        float partial = 0.0f;
#pragma unroll
        for (int nt = 0; nt < 8; nt++) {
#pragma unroll
            for (int r = 0; r < 4; r++) {
                int d = qrow + 8 * (r >> 1);
                int n = n0 + nt * 8 + qcol + (r & 1);
                float v = fmaxf(acc[mt][nt][r], 0.0f);
                if (LAYER == 0) {
                    if (n < 64)
                        g_h[((size_t)b * 64 + n) * 16 + d] = __float2half_rn(v);
                    else
                        partial = fmaf(v, s_dw[n - 64], partial);
                } else {
                    partial = fmaf(v, s_dw[64 + n], partial);
                }
            }
        }
        atomicAdd(&s_out[bl], partial);
    }
    __syncthreads();
    if (tid < 8) {
        if (LAYER == 0) out[b0 + tid] = s_out[tid] + db[0];
        else            out[b0 + tid] += s_out[tid];
    }
}

// ---------------- launch ----------------
extern "C" void kernel_launch(void* const* d_in, const int* in_sizes, int n_in,
                              void* d_out, int out_size)
{
    const float* x  = (const float*)d_in[0];   // [4096][39][16]
    const float* f0 = (const float*)d_in[1];   // [1521][128]
    const float* f1 = (const float*)d_in[2];   // [2496][128]
    const float* dw = (const float*)d_in[3];   // [192]
    const float* db = (const float*)d_in[4];   // [1]
    float* out = (float*)d_out;                // [4096]

    convert_w_kernel<0><<<(128 * K0PAD + 255) / 256, 256>>>(f0);
    convert_w_kernel<1><<<(128 * K1PAD + 255) / 256, 256>>>(f1);

    constexpr int TILE = 128 * ROWB;
    constexpr int XT_BYTES = 128 * IPADH * 2;
    constexpr int HT_BYTES = 128 * JPADH * 2;
    constexpr int OFF_T0 = ((1024 + XT_BYTES + 1023) / 1024) * 1024;              // 12288
    constexpr int OFF_T1 = ((1024 + XT_BYTES + HT_BYTES + 1023) / 1024) * 1024;   // 28672
    const int smem0 = OFF_T0 + 4 * TILE;   // 53248 (52 KB)
    const int smem1 = OFF_T1 + 4 * TILE;   // 69632 (68 KB)

    cudaFuncSetAttribute(cin_mma_kernel<39, K0TOT, K0PAD, 0>,
                         cudaFuncAttributeMaxDynamicSharedMemorySize, smem0);
    cudaFuncSetAttribute(cin_mma_kernel<64, K1TOT, K1PAD, 1>,
                         cudaFuncAttributeMaxDynamicSharedMemorySize, smem1);

    dim3 grid(B_TOT / 8);
    dim3 block(NT);
    cin_mma_kernel<39, K0TOT, K0PAD, 0><<<grid, block, smem0>>>(x, dw, db, out);
    cin_mma_kernel<64, K1TOT, K1PAD, 1><<<grid, block, smem1>>>(x, dw, db, out);
}

// round 16
// speedup vs baseline: 1.7828x; 1.1973x over previous
#include <cuda_runtime.h>
#include <cuda_fp16.h>
#include <stdint.h>

// ---------------- problem constants ----------------
#define B_TOT   4096
#define F0N     39
#define DN      16
#define NT      256

#define K0TOT   1521      // 39*39
#define K0PAD   1536      // 48 chunks of 32
#define K1TOT   2496      // 39*64
#define K1PAD   2496      // 78 chunks of 32

#define BK      32        // K per chunk (fp16 elems)
#define ROWB    80        // tile row stride bytes (64B data + 16B pad; 16B-aligned)
#define IPADH   48        // xt row stride in halves (39 data + zero tail; 96B, 16B-aligned)
#define JPADH   72        // ht row stride in halves (64 data; 144B, 16B-aligned)

// ---------------- global scratch ----------------
__device__ __half g_h[B_TOT * 64 * DN];     // fp16 h between layers
__device__ __half g_w0[128 * K0PAD];        // fp16 W, [n][KPAD], zero-padded
__device__ __half g_w1[128 * K1PAD];

// ---------------- PTX helpers ----------------
__device__ __forceinline__ uint32_t smem_to_u32(const void* p) {
    uint32_t a;
    asm("{ .reg .u64 t; cvta.to.shared.u64 t, %1; cvt.u32.u64 %0, t; }" : "=r"(a) : "l"(p));
    return a;
}

__device__ __forceinline__ void ldsm4(uint32_t* r, uint32_t addr) {
    asm volatile("ldmatrix.sync.aligned.m8n8.x4.shared.b16 {%0,%1,%2,%3}, [%4];"
        : "=r"(r[0]), "=r"(r[1]), "=r"(r[2]), "=r"(r[3]) : "r"(addr));
}

__device__ __forceinline__ void mma_f16(float* c, const uint32_t* a, uint32_t b0, uint32_t b1) {
    asm volatile(
        "mma.sync.aligned.m16n8k16.row.col.f32.f16.f16.f32 "
        "{%0,%1,%2,%3}, {%4,%5,%6,%7}, {%8,%9}, {%0,%1,%2,%3};"
        : "+f"(c[0]), "+f"(c[1]), "+f"(c[2]), "+f"(c[3])
        : "r"(a[0]), "r"(a[1]), "r"(a[2]), "r"(a[3]), "r"(b0), "r"(b1));
}

#define CP_ASYNC16(saddr, gptr) \
    asm volatile("cp.async.cg.shared.global [%0], [%1], 16;" \
        :: "r"((uint32_t)(saddr)), "l"(gptr))
#define CP_COMMIT()  asm volatile("cp.async.commit_group;" ::: "memory")
#define CP_WAIT0()   asm volatile("cp.async.wait_group 0;"  ::: "memory")

// ---------------- W convert: f[k][128] -> fp16 [n=128][KPAD], zero-padded ----------------
template<int LAYER>
__global__ void __launch_bounds__(256)
convert_w_kernel(const float* __restrict__ f)
{
    constexpr int KTOT = (LAYER == 0) ? K0TOT : K1TOT;
    constexpr int KPAD = (LAYER == 0) ? K0PAD : K1PAD;
    __half* w = (LAYER == 0) ? g_w0 : g_w1;

    int idx = blockIdx.x * blockDim.x + threadIdx.x;
    if (idx >= 128 * KPAD) return;
    int n = idx / KPAD;
    int k = idx - n * KPAD;
    float v = (k < KTOT) ? f[k * 128 + n] : 0.0f;
    w[idx] = __float2half_rn(v);
}

// ---------------- main fused layer kernel (fp16 HMMA, single-term, vectorized build) ----------------
// LAYER 0: h == x (FK=39), writes relu(z[:, :64]) to g_h (fp16), out = bias + sum z[:,64:]*dw[0:64]
// LAYER 1: h from g_h (FK=64), out += sum z * dw[64:192]
template<int FK, int KTOT, int KPAD, int LAYER>
__global__ void __launch_bounds__(NT, 2)
cin_mma_kernel(const float* __restrict__ x,
               const float* __restrict__ dw,
               const float* __restrict__ db,
               float* __restrict__ out)
{
    extern __shared__ char smem[];

    constexpr int OFF_DW   = 0;                    // 192 floats
    constexpr int OFF_SOUT = 768;                  // 8 floats
    constexpr int OFF_XT   = 1024;                 // fp16 [128][IPADH]
    constexpr int XT_BYTES = 128 * IPADH * 2;      // 12288
    constexpr int OFF_HT   = OFF_XT + XT_BYTES;    // 13312 (16B-aligned)
    constexpr int HT_BYTES = (LAYER == 1) ? 128 * JPADH * 2 : 0;
    constexpr int OFF_T    = ((OFF_HT + HT_BYTES + 1023) / 1024) * 1024;
    constexpr int TILE     = 128 * ROWB;           // 10240
    constexpr int OFF_A    = OFF_T;                // A: 2 bufs
    constexpr int OFF_B    = OFF_T + 2 * TILE;     // B: 2 bufs
    constexpr int NCHUNKS  = KPAD / BK;

    const __half* __restrict__ wsrc = (LAYER == 0) ? g_w0 : g_w1;

    const uint32_t smem_u = smem_to_u32(smem);
    float*  s_dw  = (float*)(smem + OFF_DW);
    float*  s_out = (float*)(smem + OFF_SOUT);
    __half* xt    = (__half*)(smem + OFF_XT);
    __half* ht    = (LAYER == 0) ? xt : (__half*)(smem + OFF_HT);
    constexpr int HSTR = (LAYER == 0) ? IPADH : JPADH;

    const int tid  = threadIdx.x;
    const int wid  = tid >> 5;
    const int lane = tid & 31;
    const int b0   = blockIdx.x * 8;

    const int srow = tid >> 2;     // 0..63 (+part*64)
    const int skt  = tid & 3;      // 0..3 (8 fp16 = 16B each)

    // issue B chunk into buffer pbuf via cp.async
    auto issue_b = [&](int k0n, int pbuf) {
        uint32_t bb = smem_u + OFF_B + pbuf * TILE;
#pragma unroll
        for (int p = 0; p < 2; p++) {
            int n = srow + p * 64;
            uint32_t so = (uint32_t)(n * ROWB + skt * 16);
            CP_ASYNC16(bb + so, wsrc + (size_t)n * KPAD + k0n + skt * 8);
        }
    };

    // ---- prefetch B(0) before anything else ----
    issue_b(0, 0);
    CP_COMMIT();

    // ---- zero xt padding tail (layer 0 only; disjoint from data region, no sync needed) ----
    if (LAYER == 0) {
        for (int e = tid; e < 128 * (IPADH - F0N); e += NT) {
            int r = e / (IPADH - F0N);
            int i = F0N + e - r * (IPADH - F0N);
            xt[r * IPADH + i] = __float2half(0.0f);
        }
    }
    // ---- stage x transposed (fp16): xt[row][i], row = bl*16 + d ----
    for (int e = tid; e < 8 * F0N * DN; e += NT) {
        int bl = e / (F0N * DN);
        int rem = e - bl * (F0N * DN);
        int i = rem >> 4, d = rem & 15;
        xt[(bl * 16 + d) * IPADH + i] = __float2half_rn(x[(size_t)(b0) * (F0N * DN) + e]);
    }
    if (LAYER == 1) {
        for (int e = tid; e < 8 * 64 * 16; e += NT) {
            int bl = e >> 10;
            int j  = (e >> 4) & 63;
            int d  = e & 15;
            ht[(bl * 16 + d) * JPADH + j] = g_h[(size_t)b0 * 1024 + e];
        }
    }
    if (tid < 192) s_dw[tid] = dw[tid];
    if (tid < 8)   s_out[tid] = 0.0f;
    __syncthreads();

    // build A chunk (fp16) for k-base k0n into buffer pbuf
    auto build_a = [&](int k0n, int pbuf) {
        char* Abuf = smem + OFF_A + pbuf * TILE;
        if constexpr (LAYER == 1) {
            // FK=64, BK=32: i constant per chunk, j contiguous -> vector path
            const int i  = k0n >> 6;
            const int j0 = (k0n & 63) + skt * 8;
#pragma unroll
            for (int p = 0; p < 2; p++) {
                int row = srow + p * 64;
                __half2 xv = __half2half2(xt[row * IPADH + i]);
                uint4 hv = *(const uint4*)(ht + row * JPADH + j0);
                uint32_t* hw = (uint32_t*)&hv;
                uint32_t hp[4];
#pragma unroll
                for (int v = 0; v < 4; v++) {
                    __half2 pr = __hmul2(xv, *(const __half2*)&hw[v]);
                    hp[v] = *(const uint32_t*)&pr;
                }
                *(uint4*)(Abuf + row * ROWB + skt * 16) = make_uint4(hp[0], hp[1], hp[2], hp[3]);
            }
        } else {
            // FK=39: incremental i/j walk, scalar fp16 muls (x padding zeroed)
#pragma unroll
            for (int p = 0; p < 2; p++) {
                int row = srow + p * 64;
                const __half* xr = xt + row * IPADH;
                const __half* hr = xr;    // h == x
                int kb = k0n + skt * 8;
                int i = kb / FK;
                int j = kb - i * FK;
                __half xv = xr[i];
                uint32_t hp[4];
#pragma unroll
                for (int v = 0; v < 4; v++) {
                    __half e0 = __hmul(xv, hr[j]);
                    if (++j == FK) { j = 0; xv = xr[++i]; }
                    __half e1 = __hmul(xv, hr[j]);
                    if (++j == FK) { j = 0; xv = xr[++i]; }
                    __half2 pr = __halves2half2(e0, e1);
                    hp[v] = *(const uint32_t*)&pr;
                }
                *(uint4*)(Abuf + row * ROWB + skt * 16) = make_uint4(hp[0], hp[1], hp[2], hp[3]);
            }
        }
    };

    // warp tiling: 4 (M) x 2 (N); warp tile 32 x 64
    const int wm = wid >> 1;
    const int wn = wid & 1;
    const int m0 = wm * 32;
    const int n0 = wn * 64;

    float acc[2][8][4];
#pragma unroll
    for (int mt = 0; mt < 2; mt++)
#pragma unroll
        for (int nt = 0; nt < 8; nt++)
#pragma unroll
            for (int r = 0; r < 4; r++) acc[mt][nt][r] = 0.0f;

    const int lrow = (lane & 7) + ((lane >> 3) & 1) * 8;
    const int lkb  = (lane >> 4) * 16;

    // ---- prologue: A(0); B(0) already in flight ----
    build_a(0, 0);
    CP_WAIT0();
    __syncthreads();

    for (int ch = 0; ch < NCHUNKS; ch++) {
        const int p = ch & 1;
        const bool have_next = (ch + 1 < NCHUNKS);

        // prefetch B(ch+1); lands during MMA+build below
        if (have_next) { issue_b((ch + 1) * BK, p ^ 1); CP_COMMIT(); }

        // ---- MMA phase on A(p) + B(p): 2 k16-steps ----
        const uint32_t a_u = smem_u + OFF_A + p * TILE;
        const uint32_t b_u = smem_u + OFF_B + p * TILE;
#pragma unroll
        for (int ks = 0; ks < 2; ks++) {
            const uint32_t kcb = (uint32_t)(ks * 32 + lkb);
            uint32_t av[2][4];
#pragma unroll
            for (int mt = 0; mt < 2; mt++)
                ldsm4(av[mt], a_u + (uint32_t)((m0 + mt * 16 + lrow) * ROWB) + kcb);
#pragma unroll
            for (int nt2 = 0; nt2 < 4; nt2++) {
                uint32_t rb = (uint32_t)((n0 + nt2 * 16 + lrow) * ROWB) + kcb;
                uint32_t bh[4];
                ldsm4(bh, b_u + rb);
#pragma unroll
                for (int mt = 0; mt < 2; mt++) {
#pragma unroll
                    for (int sub = 0; sub < 2; sub++) {
                        mma_f16(acc[mt][nt2 * 2 + sub], av[mt], bh[sub], bh[sub + 2]);
                    }
                }
            }
        }

        // ---- build A(ch+1) into the other buffer ----
        if (have_next) {
            build_a((ch + 1) * BK, p ^ 1);
            CP_WAIT0();                  // B(ch+1) landed
        }
        __syncthreads();                 // one barrier per chunk
    }

    // ---- epilogue: relu, h-store (layer 0, fp16), weighted reduce ----
    const int qrow = lane >> 2;
    const int qcol = (lane & 3) * 2;
#pragma unroll
    for (int mt = 0; mt < 2; mt++) {
        const int bl = wm * 2 + mt;
        const int b  = b0 + bl;
        float partial = 0.0f;
#pragma unroll
        for (int nt = 0; nt < 8; nt++) {
#pragma unroll
            for (int r = 0; r < 4; r++) {
                int d = qrow + 8 * (r >> 1);
                int n = n0 + nt * 8 + qcol + (r & 1);
                float v = fmaxf(acc[mt][nt][r], 0.0f);
                if (LAYER == 0) {
                    if (n < 64)
                        g_h[((size_t)b * 64 + n) * 16 + d] = __float2half_rn(v);
                    else
                        partial = fmaf(v, s_dw[n - 64], partial);
                } else {
                    partial = fmaf(v, s_dw[64 + n], partial);
                }
            }
        }
        atomicAdd(&s_out[bl], partial);
    }
    __syncthreads();
    if (tid < 8) {
        if (LAYER == 0) out[b0 + tid] = s_out[tid] + db[0];
        else            out[b0 + tid] += s_out[tid];
    }
}

// ---------------- launch ----------------
extern "C" void kernel_launch(void* const* d_in, const int* in_sizes, int n_in,
                              void* d_out, int out_size)
{
    const float* x  = (const float*)d_in[0];   // [4096][39][16]
    const float* f0 = (const float*)d_in[1];   // [1521][128]
    const float* f1 = (const float*)d_in[2];   // [2496][128]
    const float* dw = (const float*)d_in[3];   // [192]
    const float* db = (const float*)d_in[4];   // [1]
    float* out = (float*)d_out;                // [4096]

    convert_w_kernel<0><<<(128 * K0PAD + 255) / 256, 256>>>(f0);
    convert_w_kernel<1><<<(128 * K1PAD + 255) / 256, 256>>>(f1);

    constexpr int TILE = 128 * ROWB;
    constexpr int XT_BYTES = 128 * IPADH * 2;      // 12288
    constexpr int HT_BYTES = 128 * JPADH * 2;      // 18432
    constexpr int OFF_T0 = ((1024 + XT_BYTES + 1023) / 1024) * 1024;              // 14336
    constexpr int OFF_T1 = ((1024 + XT_BYTES + HT_BYTES + 1023) / 1024) * 1024;   // 31744
    const int smem0 = OFF_T0 + 4 * TILE;   // 55296 (54 KB)
    const int smem1 = OFF_T1 + 4 * TILE;   // 72704 (71 KB)

    cudaFuncSetAttribute(cin_mma_kernel<39, K0TOT, K0PAD, 0>,
                         cudaFuncAttributeMaxDynamicSharedMemorySize, smem0);
    cudaFuncSetAttribute(cin_mma_kernel<64, K1TOT, K1PAD, 1>,
                         cudaFuncAttributeMaxDynamicSharedMemorySize, smem1);

    dim3 grid(B_TOT / 8);
    dim3 block(NT);
    cin_mma_kernel<39, K0TOT, K0PAD, 0><<<grid, block, smem0>>>(x, dw, db, out);
    cin_mma_kernel<64, K1TOT, K1PAD, 1><<<grid, block, smem1>>>(x, dw, db, out);
}

// round 17
// speedup vs baseline: 2.2824x; 1.2802x over previous
#include <cuda_runtime.h>
#include <cuda_fp16.h>
#include <stdint.h>

// ---------------- problem constants ----------------
#define B_TOT   4096
#define F0N     39
#define DN      16
#define NT      256

#define K0TOT   1521      // 39*39 (dense)
#define K0PAD   1600      // padded k' = i*40 + j, 25 chunks of 64
#define K1TOT   2496      // 39*64
#define K1PAD   2496      // 39 chunks of 64

#define BK      64        // K per chunk (fp16 elems)
#define ROWB    144       // tile row stride bytes (128B data + 16B pad; 16B-aligned)
#define IPADH   48        // xt row stride in halves (39 data + zero tail)
#define JPADH   72        // ht row stride in halves (64 data; 144B, 16B-aligned)

// ---------------- global scratch ----------------
__device__ __half g_h[B_TOT * 64 * DN];     // fp16 h between layers
__device__ __half g_w0[128 * K0PAD];        // fp16 W0, [n][K0PAD] in padded k'-space
__device__ __half g_w1[128 * K1PAD];        // fp16 W1, [n][K1PAD]

// ---------------- PTX helpers ----------------
__device__ __forceinline__ uint32_t smem_to_u32(const void* p) {
    uint32_t a;
    asm("{ .reg .u64 t; cvta.to.shared.u64 t, %1; cvt.u32.u64 %0, t; }" : "=r"(a) : "l"(p));
    return a;
}

__device__ __forceinline__ void ldsm4(uint32_t* r, uint32_t addr) {
    asm volatile("ldmatrix.sync.aligned.m8n8.x4.shared.b16 {%0,%1,%2,%3}, [%4];"
        : "=r"(r[0]), "=r"(r[1]), "=r"(r[2]), "=r"(r[3]) : "r"(addr));
}

__device__ __forceinline__ void mma_f16(float* c, const uint32_t* a, uint32_t b0, uint32_t b1) {
    asm volatile(
        "mma.sync.aligned.m16n8k16.row.col.f32.f16.f16.f32 "
        "{%0,%1,%2,%3}, {%4,%5,%6,%7}, {%8,%9}, {%0,%1,%2,%3};"
        : "+f"(c[0]), "+f"(c[1]), "+f"(c[2]), "+f"(c[3])
        : "r"(a[0]), "r"(a[1]), "r"(a[2]), "r"(a[3]), "r"(b0), "r"(b1));
}

#define CP_ASYNC16(saddr, gptr) \
    asm volatile("cp.async.cg.shared.global [%0], [%1], 16;" \
        :: "r"((uint32_t)(saddr)), "l"(gptr))
#define CP_COMMIT()  asm volatile("cp.async.commit_group;" ::: "memory")
#define CP_WAIT0()   asm volatile("cp.async.wait_group 0;"  ::: "memory")

// ---------------- W convert ----------------
// layer 0: f0[k=i*39+j][128] -> g_w0[n][k'=i*40+j], j=39 column and tail zeroed
__global__ void __launch_bounds__(256)
convert_w0_kernel(const float* __restrict__ f)
{
    int idx = blockIdx.x * blockDim.x + threadIdx.x;
    if (idx >= 128 * K0PAD) return;
    int n  = idx / K0PAD;
    int kp = idx - n * K0PAD;
    int i = kp / 40;
    int j = kp - i * 40;
    float v = (i < 39 && j < 39) ? f[(i * 39 + j) * 128 + n] : 0.0f;
    g_w0[idx] = __float2half_rn(v);
}
// layer 1: dense copy-transpose
__global__ void __launch_bounds__(256)
convert_w1_kernel(const float* __restrict__ f)
{
    int idx = blockIdx.x * blockDim.x + threadIdx.x;
    if (idx >= 128 * K1PAD) return;
    int n = idx / K1PAD;
    int k = idx - n * K1PAD;
    g_w1[idx] = __float2half_rn(f[k * 128 + n]);
}

// ---------------- main fused layer kernel (fp16 HMMA, single-term, BK=64) ----------------
// LAYER 0: h == x (FKP=40 padded), writes relu(z[:, :64]) to g_h (fp16), out = bias + sum z[:,64:]*dw[0:64]
// LAYER 1: h from g_h (FKP=64), out += sum z * dw[64:192]
template<int FKP, int KPAD, int LAYER>
__global__ void __launch_bounds__(NT, 2)
cin_mma_kernel(const float* __restrict__ x,
               const float* __restrict__ dw,
               const float* __restrict__ db,
               float* __restrict__ out)
{
    extern __shared__ char smem[];

    constexpr int OFF_DW   = 0;                    // 192 floats
    constexpr int OFF_SOUT = 768;                  // 8 floats
    constexpr int OFF_XT   = 1024;                 // fp16 [128][IPADH]
    constexpr int XT_BYTES = 128 * IPADH * 2;      // 12288
    constexpr int OFF_HT   = OFF_XT + XT_BYTES;    // 13312 (16B-aligned)
    constexpr int HT_BYTES = (LAYER == 1) ? 128 * JPADH * 2 : 0;
    constexpr int OFF_T    = ((OFF_HT + HT_BYTES + 1023) / 1024) * 1024;
    constexpr int TILE     = 128 * ROWB;           // 18432
    constexpr int OFF_A    = OFF_T;                // A: 2 bufs
    constexpr int OFF_B    = OFF_T + 2 * TILE;     // B: 2 bufs
    constexpr int NCHUNKS  = KPAD / BK;

    const __half* __restrict__ wsrc = (LAYER == 0) ? g_w0 : g_w1;

    const uint32_t smem_u = smem_to_u32(smem);
    float*  s_dw  = (float*)(smem + OFF_DW);
    float*  s_out = (float*)(smem + OFF_SOUT);
    __half* xt    = (__half*)(smem + OFF_XT);
    __half* ht    = (LAYER == 0) ? xt : (__half*)(smem + OFF_HT);
    constexpr int HSTR = (LAYER == 0) ? IPADH : JPADH;

    const int tid  = threadIdx.x;
    const int wid  = tid >> 5;
    const int lane = tid & 31;
    const int b0   = blockIdx.x * 8;

    const int srow = tid >> 3;     // 0..31 (+part*32)
    const int skt  = tid & 7;      // 0..7 (8 fp16 = 16B each)

    // issue B chunk into buffer pbuf via cp.async
    auto issue_b = [&](int k0n, int pbuf) {
        uint32_t bb = smem_u + OFF_B + pbuf * TILE;
#pragma unroll
        for (int p = 0; p < 4; p++) {
            int n = srow + p * 32;
            uint32_t so = (uint32_t)(n * ROWB + skt * 16);
            CP_ASYNC16(bb + so, wsrc + (size_t)n * KPAD + k0n + skt * 8);
        }
    };

    // ---- prefetch B(0) before anything else ----
    issue_b(0, 0);
    CP_COMMIT();

    // ---- zero xt padding tail (both layers need x zero-tail for padded k reads) ----
    for (int e = tid; e < 128 * (IPADH - F0N); e += NT) {
        int r = e / (IPADH - F0N);
        int i = F0N + e - r * (IPADH - F0N);
        xt[r * IPADH + i] = __float2half(0.0f);
    }
    // ---- stage x transposed (fp16): xt[row][i], row = bl*16 + d ----
    for (int e = tid; e < 8 * F0N * DN; e += NT) {
        int bl = e / (F0N * DN);
        int rem = e - bl * (F0N * DN);
        int i = rem >> 4, d = rem & 15;
        xt[(bl * 16 + d) * IPADH + i] = __float2half_rn(x[(size_t)(b0) * (F0N * DN) + e]);
    }
    if (LAYER == 1) {
        for (int e = tid; e < 8 * 64 * 16; e += NT) {
            int bl = e >> 10;
            int j  = (e >> 4) & 63;
            int d  = e & 15;
            ht[(bl * 16 + d) * JPADH + j] = g_h[(size_t)b0 * 1024 + e];
        }
    }
    if (tid < 192) s_dw[tid] = dw[tid];
    if (tid < 8)   s_out[tid] = 0.0f;
    __syncthreads();

    // build A chunk (fp16) for k-base k0n into buffer pbuf.
    // k' = i*FKP + j; every 8-run (kb multiple of 8, 8|FKP) stays within one i.
    auto build_a = [&](int k0n, int pbuf) {
        char* Abuf = smem + OFF_A + pbuf * TILE;
        const int kb = k0n + skt * 8;
        const int i  = kb / FKP;            // constant per thread per chunk
        const int j0 = kb - i * FKP;
#pragma unroll
        for (int p = 0; p < 4; p++) {
            int row = srow + p * 32;
            __half2 xv = __half2half2(xt[row * IPADH + i]);
            uint4 hv = *(const uint4*)(ht + row * HSTR + j0);
            uint32_t* hw = (uint32_t*)&hv;
            uint32_t hp[4];
#pragma unroll
            for (int v = 0; v < 4; v++) {
                __half2 pr = __hmul2(xv, *(const __half2*)&hw[v]);
                hp[v] = *(const uint32_t*)&pr;
            }
            *(uint4*)(Abuf + row * ROWB + skt * 16) = make_uint4(hp[0], hp[1], hp[2], hp[3]);
        }
    };

    // warp tiling: 4 (M) x 2 (N); warp tile 32 x 64
    const int wm = wid >> 1;
    const int wn = wid & 1;
    const int m0 = wm * 32;
    const int n0 = wn * 64;

    float acc[2][8][4];
#pragma unroll
    for (int mt = 0; mt < 2; mt++)
#pragma unroll
        for (int nt = 0; nt < 8; nt++)
#pragma unroll
            for (int r = 0; r < 4; r++) acc[mt][nt][r] = 0.0f;

    const int lrow = (lane & 7) + ((lane >> 3) & 1) * 8;
    const int lkb  = (lane >> 4) * 16;

    // ---- prologue: A(0); B(0) already in flight ----
    build_a(0, 0);
    CP_WAIT0();
    __syncthreads();

    for (int ch = 0; ch < NCHUNKS; ch++) {
        const int p = ch & 1;
        const bool have_next = (ch + 1 < NCHUNKS);

        // prefetch B(ch+1); lands during MMA+build below
        if (have_next) { issue_b((ch + 1) * BK, p ^ 1); CP_COMMIT(); }

        // ---- MMA phase on A(p) + B(p): 4 k16-steps ----
        const uint32_t a_u = smem_u + OFF_A + p * TILE;
        const uint32_t b_u = smem_u + OFF_B + p * TILE;
#pragma unroll
        for (int ks = 0; ks < 4; ks++) {
            const uint32_t kcb = (uint32_t)(ks * 32 + lkb);
            uint32_t av[2][4];
#pragma unroll
            for (int mt = 0; mt < 2; mt++)
                ldsm4(av[mt], a_u + (uint32_t)((m0 + mt * 16 + lrow) * ROWB) + kcb);
#pragma unroll
            for (int nt2 = 0; nt2 < 4; nt2++) {
                uint32_t rb = (uint32_t)((n0 + nt2 * 16 + lrow) * ROWB) + kcb;
                uint32_t bh[4];
                ldsm4(bh, b_u + rb);
#pragma unroll
                for (int mt = 0; mt < 2; mt++) {
#pragma unroll
                    for (int sub = 0; sub < 2; sub++) {
                        mma_f16(acc[mt][nt2 * 2 + sub], av[mt], bh[sub], bh[sub + 2]);
                    }
                }
            }
        }

        // ---- build A(ch+1) into the other buffer ----
        if (have_next) {
            build_a((ch + 1) * BK, p ^ 1);
            CP_WAIT0();                  // B(ch+1) landed
        }
        __syncthreads();                 // one barrier per chunk
    }

    // ---- epilogue: relu, h-store (layer 0, fp16), weighted reduce ----
    const int qrow = lane >> 2;
    const int qcol = (lane & 3) * 2;
#pragma unroll
    for (int mt = 0; mt < 2; mt++) {
        const int bl = wm * 2 + mt;
        const int b  = b0 + bl;
        float partial = 0.0f;
#pragma unroll
        for (int nt = 0; nt < 8; nt++) {
#pragma unroll
            for (int r = 0; r < 4; r++) {
                int d = qrow + 8 * (r >> 1);
                int n = n0 + nt * 8 + qcol + (r & 1);
                float v = fmaxf(acc[mt][nt][r], 0.0f);
                if (LAYER == 0) {
                    if (n < 64)
                        g_h[((size_t)b * 64 + n) * 16 + d] = __float2half_rn(v);
                    else
                        partial = fmaf(v, s_dw[n - 64], partial);
                } else {
                    partial = fmaf(v, s_dw[64 + n], partial);
                }
            }
        }
        atomicAdd(&s_out[bl], partial);
    }
    __syncthreads();
    if (tid < 8) {
        if (LAYER == 0) out[b0 + tid] = s_out[tid] + db[0];
        else            out[b0 + tid] += s_out[tid];
    }
}

// ---------------- launch ----------------
extern "C" void kernel_launch(void* const* d_in, const int* in_sizes, int n_in,
                              void* d_out, int out_size)
{
    const float* x  = (const float*)d_in[0];   // [4096][39][16]
    const float* f0 = (const float*)d_in[1];   // [1521][128]
    const float* f1 = (const float*)d_in[2];   // [2496][128]
    const float* dw = (const float*)d_in[3];   // [192]
    const float* db = (const float*)d_in[4];   // [1]
    float* out = (float*)d_out;                // [4096]

    convert_w0_kernel<<<(128 * K0PAD + 255) / 256, 256>>>(f0);
    convert_w1_kernel<<<(128 * K1PAD + 255) / 256, 256>>>(f1);

    constexpr int TILE = 128 * ROWB;               // 18432
    constexpr int XT_BYTES = 128 * IPADH * 2;      // 12288
    constexpr int HT_BYTES = 128 * JPADH * 2;      // 18432
    constexpr int OFF_T0 = ((1024 + XT_BYTES + 1023) / 1024) * 1024;              // 14336
    constexpr int OFF_T1 = ((1024 + XT_BYTES + HT_BYTES + 1023) / 1024) * 1024;   // 31744
    const int smem0 = OFF_T0 + 4 * TILE;   // 88064  (86 KB)  -> 2 CTAs/SM
    const int smem1 = OFF_T1 + 4 * TILE;   // 105472 (103 KB) -> 2 CTAs/SM

    cudaFuncSetAttribute(cin_mma_kernel<40, K0PAD, 0>,
                         cudaFuncAttributeMaxDynamicSharedMemorySize, smem0);
    cudaFuncSetAttribute(cin_mma_kernel<64, K1PAD, 1>,
                         cudaFuncAttributeMaxDynamicSharedMemorySize, smem1);

    dim3 grid(B_TOT / 8);
    dim3 block(NT);
    cin_mma_kernel<40, K0PAD, 0><<<grid, block, smem0>>>(x, dw, db, out);
    cin_mma_kernel<64, K1PAD, 1><<<grid, block, smem1>>>(x, dw, db, out);
}